// round 1
// baseline (speedup 1.0000x reference)
#include <cuda_runtime.h>
#include <cstdint>

// Problem constants
#define BB 32
#define NN 1024
#define DD 512
#define KK 64
#define EPSF 1e-12f

// ---------------- scratch (static device allocations; no cudaMalloc) --------
__device__ float g_P[BB * NN * KK];        // softmax probs [B,N,K]
__device__ float g_vlad[BB * KK * DD];     // raw vlad [B,K,D]
__device__ float g_asum[BB * KK];          // a_sum [B,K]
__device__ float g_rs[BB * KK];            // per-(b,k) intra-norm scale
__device__ float g_gn[BB];                 // per-b global sum of squares

// ---------------- packed f32x2 helpers (Blackwell) ---------------------------
__device__ __forceinline__ void fma2(unsigned long long& d,
                                     unsigned long long a,
                                     unsigned long long b) {
    asm("fma.rn.f32x2 %0, %1, %2, %0;" : "+l"(d) : "l"(a), "l"(b));
}
__device__ __forceinline__ unsigned long long pack2(float lo, float hi) {
    unsigned long long r;
    asm("mov.b64 %0, {%1, %2};" : "=l"(r) : "f"(lo), "f"(hi));
    return r;
}
__device__ __forceinline__ float2 unpack2(unsigned long long v) {
    float2 f;
    asm("mov.b64 {%0, %1}, %2;" : "=f"(f.x), "=f"(f.y) : "l"(v));
    return f;
}

// ---------------- kernel 1: softmax over K + a_sum ---------------------------
// one warp per row; block = 8 rows (all same b since N % 8 == 0)
__global__ void __launch_bounds__(256) k_softmax(const float* __restrict__ bn,
                                                 float* __restrict__ P,
                                                 float* __restrict__ asum) {
    __shared__ float sAcc[KK];
    int tid = threadIdx.x;
    int w = tid >> 5;
    int lane = tid & 31;
    int row = blockIdx.x * 8 + w;          // 0..32767
    if (tid < KK) sAcc[tid] = 0.f;
    __syncthreads();

    const float* r = bn + (size_t)row * KK;
    float v0 = r[lane];
    float v1 = r[lane + 32];
    float m = fmaxf(v0, v1);
#pragma unroll
    for (int o = 16; o; o >>= 1) m = fmaxf(m, __shfl_xor_sync(0xffffffffu, m, o));
    float e0 = __expf(v0 - m);
    float e1 = __expf(v1 - m);
    float s = e0 + e1;
#pragma unroll
    for (int o = 16; o; o >>= 1) s += __shfl_xor_sync(0xffffffffu, s, o);
    float inv = 1.f / s;
    float p0 = e0 * inv;
    float p1 = e1 * inv;
    P[(size_t)row * KK + lane] = p0;
    P[(size_t)row * KK + lane + 32] = p1;
    atomicAdd(&sAcc[lane], p0);
    atomicAdd(&sAcc[lane + 32], p1);
    __syncthreads();
    if (tid < KK) atomicAdd(&asum[(blockIdx.x >> 7) * KK + tid], sAcc[tid]);
}

// ---------------- kernel 2: vlad[b,k,d] = sum_n P[b,n,k] * x[b,n,d] ----------
// grid (B, D/128); block 256 = 16(ty:k) x 16(tx:d); microtile 4k x 8d (f32x2)
#define DT 128
#define NC 32
__global__ void __launch_bounds__(256, 1) k_gemm(const float* __restrict__ Pg,
                                                 const float* __restrict__ xg,
                                                 float* __restrict__ vlad) {
    __shared__ float sP[NC][KK];     // 8 KB
    __shared__ float sX[NC][DT];     // 16 KB
    const int tid = threadIdx.x;
    const int tx = tid & 15;         // d group
    const int ty = tid >> 4;         // k group
    const int b = blockIdx.x;
    const int d0 = blockIdx.y * DT;
    const int bN = b * NN;

    unsigned long long acc[4][4];
#pragma unroll
    for (int i = 0; i < 4; i++)
#pragma unroll
        for (int j = 0; j < 4; j++) acc[i][j] = 0ull;

    float4 rp[2], rx[4];

    // prefetch chunk 0
#pragma unroll
    for (int j = 0; j < 2; j++) {
        int f = j * 256 + tid;
        int row = f >> 4, c = (f & 15) << 2;
        rp[j] = *(const float4*)&Pg[(((size_t)(bN + row)) << 6) + c];
    }
#pragma unroll
    for (int j = 0; j < 4; j++) {
        int f = j * 256 + tid;
        int row = f >> 5, c = (f & 31) << 2;
        rx[j] = *(const float4*)&xg[(((size_t)(bN + row)) << 9) + d0 + c];
    }

    for (int n0 = 0; n0 < NN; n0 += NC) {
        __syncthreads();
#pragma unroll
        for (int j = 0; j < 2; j++) {
            int f = j * 256 + tid;
            int row = f >> 4, c = (f & 15) << 2;
            *(float4*)&sP[row][c] = rp[j];
        }
#pragma unroll
        for (int j = 0; j < 4; j++) {
            int f = j * 256 + tid;
            int row = f >> 5, c = (f & 31) << 2;
            *(float4*)&sX[row][c] = rx[j];
        }
        __syncthreads();

        if (n0 + NC < NN) {  // prefetch next chunk while computing
            int nn = n0 + NC;
#pragma unroll
            for (int j = 0; j < 2; j++) {
                int f = j * 256 + tid;
                int row = f >> 4, c = (f & 15) << 2;
                rp[j] = *(const float4*)&Pg[(((size_t)(bN + nn + row)) << 6) + c];
            }
#pragma unroll
            for (int j = 0; j < 4; j++) {
                int f = j * 256 + tid;
                int row = f >> 5, c = (f & 31) << 2;
                rx[j] = *(const float4*)&xg[(((size_t)(bN + nn + row)) << 9) + d0 + c];
            }
        }

#pragma unroll
        for (int i = 0; i < NC; i++) {
            float4 p = *(const float4*)&sP[i][ty << 2];
            float4 xa = *(const float4*)&sX[i][tx << 3];
            float4 xb = *(const float4*)&sX[i][(tx << 3) + 4];
            unsigned long long xp[4];
            xp[0] = pack2(xa.x, xa.y);
            xp[1] = pack2(xa.z, xa.w);
            xp[2] = pack2(xb.x, xb.y);
            xp[3] = pack2(xb.z, xb.w);
            unsigned long long pd[4];
            pd[0] = pack2(p.x, p.x);
            pd[1] = pack2(p.y, p.y);
            pd[2] = pack2(p.z, p.z);
            pd[3] = pack2(p.w, p.w);
#pragma unroll
            for (int kk = 0; kk < 4; kk++)
#pragma unroll
                for (int jj = 0; jj < 4; jj++) fma2(acc[kk][jj], pd[kk], xp[jj]);
        }
    }

    // write out tile
#pragma unroll
    for (int kk = 0; kk < 4; kk++) {
        float2 a0 = unpack2(acc[kk][0]);
        float2 a1 = unpack2(acc[kk][1]);
        float2 a2 = unpack2(acc[kk][2]);
        float2 a3 = unpack2(acc[kk][3]);
        float4 w0 = make_float4(a0.x, a0.y, a1.x, a1.y);
        float4 w1 = make_float4(a2.x, a2.y, a3.x, a3.y);
        size_t base = ((size_t)(b * KK + (ty << 2) + kk)) * DD + d0 + (tx << 3);
        *(float4*)&vlad[base] = w0;
        *(float4*)&vlad[base + 4] = w1;
    }
}

// ---------------- kernel 3: per-(b,k) residual sumsq -> scale, global sumsq --
__global__ void __launch_bounds__(128) k_rowstat(const float* __restrict__ vlad,
                                                 const float* __restrict__ asum,
                                                 const float* __restrict__ c2,
                                                 float* __restrict__ rs,
                                                 float* __restrict__ gn) {
    int bk = blockIdx.x;        // b*64 + k
    int b = bk >> 6;
    int k = bk & 63;
    float a = asum[bk];
    const float* vr = vlad + (size_t)bk * DD;
    float ss = 0.f;
#pragma unroll
    for (int j = threadIdx.x; j < DD; j += 128) {
        float v = vr[j] - a * c2[j * KK + k];   // clusters2[0, d, k]
        ss += v * v;
    }
#pragma unroll
    for (int o = 16; o; o >>= 1) ss += __shfl_xor_sync(0xffffffffu, ss, o);
    __shared__ float sw[4];
    if ((threadIdx.x & 31) == 0) sw[threadIdx.x >> 5] = ss;
    __syncthreads();
    if (threadIdx.x == 0) {
        float t = sw[0] + sw[1] + sw[2] + sw[3];
        float sc = rsqrtf(t + EPSF);
        rs[bk] = sc;
        atomicAdd(&gn[b], t * sc * sc);
    }
}

// ---------------- kernel 4: normalize + transpose [B,K,D] -> [B, D*K] --------
__global__ void k_final(const float* __restrict__ vlad,
                        const float* __restrict__ asum,
                        const float* __restrict__ c2,
                        const float* __restrict__ rs,
                        const float* __restrict__ gn,
                        float* __restrict__ out) {
    int b = blockIdx.x;
    int dt = blockIdx.y;     // 0..15
    int kt = blockIdx.z;     // 0..1
    __shared__ float t[32][33];
    int tx = threadIdx.x;    // 0..31
    int ty = threadIdx.y;    // 0..7
#pragma unroll
    for (int r = 0; r < 4; r++) {
        int kl = ty + 8 * r;
        int k = kt * 32 + kl;
        int d = dt * 32 + tx;
        int bk = b * KK + k;
        float v = (vlad[(size_t)bk * DD + d] - asum[bk] * c2[d * KK + k]) * rs[bk];
        t[kl][tx] = v;
    }
    __syncthreads();
    float g = rsqrtf(gn[b] + EPSF);
#pragma unroll
    for (int r = 0; r < 4; r++) {
        int dl = ty + 8 * r;
        int d = dt * 32 + dl;
        int k = kt * 32 + tx;
        out[(size_t)b * (DD * KK) + d * KK + k] = t[tx][dl] * g;
    }
}

// ---------------- launcher ---------------------------------------------------
extern "C" void kernel_launch(void* const* d_in, const int* in_sizes, int n_in,
                              void* d_out, int out_size) {
    const float* x = (const float*)d_in[0];     // [B,N,D]
    const float* bn = (const float*)d_in[1];    // [B*N,K]
    const float* c2 = (const float*)d_in[2];    // [1,D,K]
    float* out = (float*)d_out;

    float *Pp, *vlad, *asum, *rs, *gn;
    cudaGetSymbolAddress((void**)&Pp, g_P);
    cudaGetSymbolAddress((void**)&vlad, g_vlad);
    cudaGetSymbolAddress((void**)&asum, g_asum);
    cudaGetSymbolAddress((void**)&rs, g_rs);
    cudaGetSymbolAddress((void**)&gn, g_gn);

    cudaMemsetAsync(asum, 0, BB * KK * sizeof(float));
    cudaMemsetAsync(gn, 0, BB * sizeof(float));

    k_softmax<<<(BB * NN) / 8, 256>>>(bn, Pp, asum);
    k_gemm<<<dim3(BB, DD / DT), 256>>>(Pp, x, vlad);
    k_rowstat<<<BB * KK, 128>>>(vlad, asum, c2, rs, gn);
    k_final<<<dim3(BB, DD / 32, KK / 32), dim3(32, 8)>>>(vlad, asum, c2, rs, gn, out);
}